// round 1
// baseline (speedup 1.0000x reference)
#include <cuda_runtime.h>
#include <cuda_bf16.h>

// Problem constants
#define NBS   256   // B*S = 16*16
#define LSEQ  128   // L
#define NA    8     // A
#define NT    8     // T
#define DIM   768   // D
#define DCHUNK 256  // columns handled per CTA (DIM / gridDim.y)
#define NPAIR 24    // 3 arg types * A

__global__ __launch_bounds__(256)
void slmuse_fused_kernel(const int* __restrict__ sentence_ids,
                         const int* __restrict__ attention_masks,
                         const int* __restrict__ predicate_ids,
                         const int* __restrict__ arg0_ids,
                         const int* __restrict__ arg1_ids,
                         const float* __restrict__ emb,
                         float* __restrict__ out)
{
    const int bs    = blockIdx.x;   // 0..255 (b*S+s)
    const int chunk = blockIdx.y;   // 0..2   column chunk
    const int tid   = threadIdx.x;  // 0..255

    __shared__ int   s_sid[LSEQ];
    __shared__ float s_mask[LSEQ];
    __shared__ int   s_ids[3][NA * NT];
    __shared__ float s_w[NPAIR][LSEQ];
    __shared__ float s_wlist[NPAIR][LSEQ];
    __shared__ int   s_llist[NPAIR][LSEQ];
    __shared__ int   s_nnz[NPAIR];
    __shared__ float s_cnt[NPAIR];
    __shared__ float s_maskcnt;

    // ---- Phase 0: load ids / mask into smem ----
    if (tid < LSEQ) {
        s_sid[tid]  = sentence_ids[bs * LSEQ + tid];
        s_mask[tid] = (float)attention_masks[bs * LSEQ + tid];
    }
    if (tid < NA * NT) {
        s_ids[0][tid] = predicate_ids[bs * (NA * NT) + tid];
        s_ids[1][tid] = arg0_ids[bs * (NA * NT) + tid];
        s_ids[2][tid] = arg1_ids[bs * (NA * NT) + tid];
    }
    __syncthreads();

    // ---- Phase 1a: dense weights w[j][l] = #tokens of pair j matching sid[l] ----
    for (int idx = tid; idx < NPAIR * LSEQ; idx += 256) {
        const int j = idx >> 7;        // pair 0..23
        const int l = idx & (LSEQ - 1);
        const int sv = s_sid[l];
        const int* ids = &s_ids[j >> 3][(j & 7) * NT];
        int w = 0;
#pragma unroll
        for (int t = 0; t < NT; t++) {
            const int av = ids[t];
            w += (av != 0 && av == sv) ? 1 : 0;
        }
        s_w[j][l] = (float)w;
    }
    __syncthreads();

    // ---- Phase 1b: compact nonzero lists (24 threads) + mask count (thread 24) ----
    if (tid < NPAIR) {
        int nz = 0;
        float c = 0.0f;
        for (int l = 0; l < LSEQ; l++) {
            const float wv = s_w[tid][l];
            if (wv != 0.0f) {
                s_wlist[tid][nz] = wv;
                s_llist[tid][nz] = l;
                nz++;
                c += wv;
            }
        }
        s_nnz[tid] = nz;
        s_cnt[tid] = c;
    } else if (tid == NPAIR) {
        float c = 0.0f;
        for (int l = 0; l < LSEQ; l++) c += s_mask[l];
        s_maskcnt = c;
    }
    __syncthreads();

    // ---- Phase 2: mean pool (stream the slab once). One column per thread. ----
    {
        const int d = chunk * DCHUNK + tid;
        const float* e = emb + (size_t)bs * LSEQ * DIM + d;
        float a0 = 0.f, a1 = 0.f, a2 = 0.f, a3 = 0.f;
#pragma unroll 4
        for (int l = 0; l < LSEQ; l += 4) {
            a0 += s_mask[l + 0] * e[(size_t)(l + 0) * DIM];
            a1 += s_mask[l + 1] * e[(size_t)(l + 1) * DIM];
            a2 += s_mask[l + 2] * e[(size_t)(l + 2) * DIM];
            a3 += s_mask[l + 3] * e[(size_t)(l + 3) * DIM];
        }
        const float sum = (a0 + a1) + (a2 + a3);
        const float denom = fmaxf(s_maskcnt, 1.0f);
        out[bs * DIM + d] = sum / denom;
    }

    // ---- Phase 3: arg embeddings via compacted gather (rows hot in L1/L2) ----
    {
        const int warp = tid >> 5;
        const int lane = tid & 31;
        const float* base = emb + (size_t)bs * LSEQ * DIM + chunk * DCHUNK + lane;

        for (int r = 0; r < 3; r++) {
            const int j = warp + 8 * r;           // pair, uniform per warp
            float acc[DCHUNK / 32];
#pragma unroll
            for (int k = 0; k < DCHUNK / 32; k++) acc[k] = 0.0f;

            const int nz = s_nnz[j];
            for (int i = 0; i < nz; i++) {
                const int l = s_llist[j][i];
                const float wv = s_wlist[j][i];
                const float* row = base + (size_t)l * DIM;
#pragma unroll
                for (int k = 0; k < DCHUNK / 32; k++)
                    acc[k] += wv * row[k * 32];
            }

            const float inv = 1.0f / fmaxf(s_cnt[j], 1.0f);  // zero-match case: acc==0 anyway
            const int tt = j >> 3;     // 0=predicate, 1=arg0, 2=arg1
            const int a  = j & 7;
            float* op = out + NBS * DIM                    // skip mean-pool output
                        + tt * (NBS * NA * DIM)
                        + (bs * NA + a) * DIM
                        + chunk * DCHUNK + lane;
#pragma unroll
            for (int k = 0; k < DCHUNK / 32; k++)
                op[k * 32] = acc[k] * inv;
        }
    }
}

extern "C" void kernel_launch(void* const* d_in, const int* in_sizes, int n_in,
                              void* d_out, int out_size)
{
    const int*   sid  = (const int*)d_in[0];
    const int*   am   = (const int*)d_in[1];
    const int*   pred = (const int*)d_in[2];
    const int*   a0   = (const int*)d_in[3];
    const int*   a1   = (const int*)d_in[4];
    const float* emb  = (const float*)d_in[5];
    float* out = (float*)d_out;

    dim3 grid(NBS, DIM / DCHUNK);  // 256 x 3
    slmuse_fused_kernel<<<grid, 256>>>(sid, am, pred, a0, a1, emb, out);
}

// round 3
// speedup vs baseline: 1.4822x; 1.4822x over previous
#include <cuda_runtime.h>
#include <cuda_bf16.h>

#define NBS   256   // B*S
#define LSEQ  128   // L
#define NA    8
#define NT    8
#define DIM   768   // D
#define CCH   128   // columns per CTA chunk
#define NCH   (DIM / CCH)   // 6
#define ROWF4 (DIM / 4)     // 192 float4 per row
#define NPAIR 24

__global__ __launch_bounds__(256)
void slmuse_fused_kernel(const int* __restrict__ sentence_ids,
                         const int* __restrict__ attention_masks,
                         const int* __restrict__ predicate_ids,
                         const int* __restrict__ arg0_ids,
                         const int* __restrict__ arg1_ids,
                         const float* __restrict__ emb,
                         float* __restrict__ out)
{
    const int bs    = blockIdx.x;    // 0..255
    const int chunk = blockIdx.y;    // 0..5
    const int tid   = threadIdx.x;
    const int warp  = tid >> 5;      // 0..7
    const int lane  = tid & 31;

    __shared__ int    s_sid[LSEQ];
    __shared__ float  s_mask[LSEQ];
    __shared__ int    s_ids[3][NA * NT];
    __shared__ short  s_list[NPAIR][LSEQ];   // packed (w<<8)|l
    __shared__ int    s_nnz[NPAIR];
    __shared__ float  s_inv[NPAIR];
    __shared__ float  s_invmask;
    __shared__ float4 s_red[256];

    // ---- load ids / mask ----
    if (tid < LSEQ) {
        s_sid[tid]  = sentence_ids[bs * LSEQ + tid];
        s_mask[tid] = (float)attention_masks[bs * LSEQ + tid];
    }
    if (tid < NA * NT) {
        s_ids[0][tid] = predicate_ids[bs * (NA * NT) + tid];
        s_ids[1][tid] = arg0_ids[bs * (NA * NT) + tid];
        s_ids[2][tid] = arg1_ids[bs * (NA * NT) + tid];
    }
    __syncthreads();

    // ---- ballot compaction: warp w handles pairs w, w+8, w+16 ----
#pragma unroll
    for (int r = 0; r < 3; r++) {
        const int j = warp + 8 * r;
        int tok[NT];
#pragma unroll
        for (int t = 0; t < NT; t++) tok[t] = s_ids[r][warp * NT + t];

        int nz = 0;
        float cnt = 0.0f;
#pragma unroll
        for (int lb = 0; lb < LSEQ; lb += 32) {
            const int l  = lb + lane;
            const int sv = s_sid[l];
            int w = 0;
#pragma unroll
            for (int t = 0; t < NT; t++)
                w += (tok[t] != 0 && tok[t] == sv) ? 1 : 0;
            const unsigned m = __ballot_sync(0xffffffffu, w > 0);
            if (w > 0) {
                const int pos = nz + __popc(m & ((1u << lane) - 1u));
                s_list[j][pos] = (short)((w << 8) | l);
            }
            nz  += __popc(m);
            cnt += (float)w;
        }
#pragma unroll
        for (int off = 16; off; off >>= 1)
            cnt += __shfl_xor_sync(0xffffffffu, cnt, off);
        if (lane == 0) { s_nnz[j] = nz; s_inv[j] = 1.0f / fmaxf(cnt, 1.0f); }
    }
    if (warp == 0) {
        float c = s_mask[lane] + s_mask[lane + 32] + s_mask[lane + 64] + s_mask[lane + 96];
#pragma unroll
        for (int off = 16; off; off >>= 1)
            c += __shfl_xor_sync(0xffffffffu, c, off);
        if (lane == 0) s_invmask = 1.0f / fmaxf(c, 1.0f);
    }
    __syncthreads();

    const float4* ebase =
        (const float4*)(emb + (size_t)bs * LSEQ * DIM + chunk * CCH);

    // ---- phase 2: mean pool. warp = L-group (16 rows), lane = float4 column ----
    {
        float4 a0 = {0,0,0,0}, a1 = {0,0,0,0}, a2 = {0,0,0,0}, a3 = {0,0,0,0};
#pragma unroll
        for (int i = 0; i < 16; i += 4) {
            const int l0 = warp * 16 + i;
            const float4 v0 = ebase[(size_t)(l0 + 0) * ROWF4 + lane];
            const float4 v1 = ebase[(size_t)(l0 + 1) * ROWF4 + lane];
            const float4 v2 = ebase[(size_t)(l0 + 2) * ROWF4 + lane];
            const float4 v3 = ebase[(size_t)(l0 + 3) * ROWF4 + lane];
            const float m0 = s_mask[l0 + 0], m1 = s_mask[l0 + 1];
            const float m2 = s_mask[l0 + 2], m3 = s_mask[l0 + 3];
            a0.x += m0 * v0.x; a0.y += m0 * v0.y; a0.z += m0 * v0.z; a0.w += m0 * v0.w;
            a1.x += m1 * v1.x; a1.y += m1 * v1.y; a1.z += m1 * v1.z; a1.w += m1 * v1.w;
            a2.x += m2 * v2.x; a2.y += m2 * v2.y; a2.z += m2 * v2.z; a2.w += m2 * v2.w;
            a3.x += m3 * v3.x; a3.y += m3 * v3.y; a3.z += m3 * v3.z; a3.w += m3 * v3.w;
        }
        float4 s;
        s.x = (a0.x + a1.x) + (a2.x + a3.x);
        s.y = (a0.y + a1.y) + (a2.y + a3.y);
        s.z = (a0.z + a1.z) + (a2.z + a3.z);
        s.w = (a0.w + a1.w) + (a2.w + a3.w);
        s_red[tid] = s;
    }
    __syncthreads();

    if (tid < 32) {
        float4 s = {0,0,0,0};
#pragma unroll
        for (int g = 0; g < 8; g++) {
            const float4 v = s_red[g * 32 + tid];
            s.x += v.x; s.y += v.y; s.z += v.z; s.w += v.w;
        }
        const float inv = s_invmask;
        float4 o; o.x = s.x * inv; o.y = s.y * inv; o.z = s.z * inv; o.w = s.w * inv;
        ((float4*)(out + bs * DIM + chunk * CCH))[tid] = o;
    }

    // ---- phase 3: arg embeddings via compacted float4 gathers (hot in L1/L2) ----
#pragma unroll
    for (int r = 0; r < 3; r++) {
        const int j = warp + 8 * r;
        float4 acc = {0,0,0,0};
        const int nz = s_nnz[j];
        for (int i = 0; i < nz; i++) {
            const int p = (int)s_list[j][i];
            const int l = p & 255;
            const float w = (float)(p >> 8);
            const float4 v = ebase[(size_t)l * ROWF4 + lane];
            acc.x += w * v.x; acc.y += w * v.y; acc.z += w * v.z; acc.w += w * v.w;
        }
        const float inv = s_inv[j];
        float4 o;
        o.x = acc.x * inv; o.y = acc.y * inv; o.z = acc.z * inv; o.w = acc.w * inv;
        float* op = out + NBS * DIM
                    + r * (NBS * NA * DIM)
                    + (bs * NA + warp) * DIM
                    + chunk * CCH;
        ((float4*)op)[lane] = o;
    }
}

extern "C" void kernel_launch(void* const* d_in, const int* in_sizes, int n_in,
                              void* d_out, int out_size)
{
    const int*   sid  = (const int*)d_in[0];
    const int*   am   = (const int*)d_in[1];
    const int*   pred = (const int*)d_in[2];
    const int*   a0   = (const int*)d_in[3];
    const int*   a1   = (const int*)d_in[4];
    const float* emb  = (const float*)d_in[5];
    float* out = (float*)d_out;

    dim3 grid(NBS, NCH);   // 256 x 6
    slmuse_fused_kernel<<<grid, 256>>>(sid, am, pred, a0, a1, emb, out);
}